// round 14
// baseline (speedup 1.0000x reference)
#include <cuda_runtime.h>
#include <cuda_fp16.h>
#include <cstdint>
#include <cstddef>

#define T_LEN 16384
#define L_LAB 1024
#define LOG2E 1.4426950408889634f
#define LN2_D 0.6931471805599453
#define CSIZE 16           // cluster size (16 SMs do all the work)
#define TPB   1024
#define ROWS_PER_BLK 64    // L_LAB / CSIZE

// ---- persistent scratch (no allocations allowed) ----
__device__ float  g_alpha[L_LAB];
__device__ double g_csum;
__device__ double g_gold;

static __device__ __forceinline__ float ex2f(float x) {
    float r; asm("ex2.approx.ftz.f32 %0, %1;" : "=f"(r) : "f"(x)); return r;
}
static __device__ __forceinline__ float lg2f_(float x) {
    float r; asm("lg2.approx.f32 %0, %1;" : "=f"(r) : "f"(x)); return r;
}
static __device__ __forceinline__ unsigned smem_u32(const void* p) {
    unsigned a;
    asm("{ .reg .u64 t; cvta.to.shared.u64 t, %1; cvt.u32.u64 %0, t; }"
        : "=r"(a) : "l"(p));
    return a;
}
static __device__ __forceinline__ void st_dsmem64(unsigned localAddr, unsigned peer,
                                                  unsigned long long v) {
    unsigned r;
    asm volatile("mapa.shared::cluster.u32 %0, %1, %2;" : "=r"(r) : "r"(localAddr), "r"(peer));
    asm volatile("st.shared::cluster.b64 [%0], %1;" :: "r"(r), "l"(v) : "memory");
}
// Release-arrive on the mbarrier at `localAddr`'s offset in CTA `peer`.
// The release (cluster scope) publishes this warp's prior DSMEM stores
// (ordered into this lane via the preceding __syncwarp).
static __device__ __forceinline__ void mbar_arrive_peer(unsigned localAddr, unsigned peer) {
    unsigned r;
    asm volatile("mapa.shared::cluster.u32 %0, %1, %2;" : "=r"(r) : "r"(localAddr), "r"(peer));
    asm volatile("mbarrier.arrive.release.cluster.shared::cluster.b64 _, [%0];"
                 :: "r"(r) : "memory");
}
// Acquire-wait (cluster scope) on a local mbarrier for the given phase parity.
static __device__ __forceinline__ void mbar_wait_cluster(unsigned addr, unsigned parity) {
    asm volatile(
        "{\n\t"
        ".reg .pred P;\n"
        "WAIT_%=: \n\t"
        "mbarrier.try_wait.parity.acquire.cluster.shared::cta.b64 P, [%0], %1, 0x989680;\n\t"
        "@P bra.uni DONE_%=;\n\t"
        "bra.uni WAIT_%=;\n"
        "DONE_%=: \n\t"
        "}"
        :: "r"(addr), "r"(parity) : "memory");
}
#define CLUSTER_SYNC() do { \
    asm volatile("barrier.cluster.arrive.aligned;" ::: "memory"); \
    asm volatile("barrier.cluster.wait.aligned;"   ::: "memory"); \
} while (0)

// Grid (16, 2), cluster (16,1,1):
//   y==0: the compute cluster (one CTA per SM, 1024 threads).
//   y==1, x==0: gold-path score; other y==1 blocks exit (their cluster never syncs).
__global__ void __launch_bounds__(TPB, 1) __cluster_dims__(CSIZE, 1, 1)
crf_main(const float* __restrict__ pred,
         const int*   __restrict__ ref,
         const float* __restrict__ trans)
{
    if (blockIdx.y == 1) {
        if (blockIdx.x != 0) return;
        __shared__ double red[TPB];
        int tid = threadIdx.x;
        double g = 0.0;
        for (int t = tid; t < T_LEN; t += TPB) {
            int r = __ldg(&ref[t]);
            int p = (t == 0) ? (L_LAB - 2) : __ldg(&ref[t - 1]);
            g += (double)__ldg(&pred[(size_t)t * L_LAB + r])
               + (double)__ldg(&trans[(size_t)r * L_LAB + p]);
        }
        red[tid] = g; __syncthreads();
        for (int s = TPB / 2; s > 0; s >>= 1) {
            if (tid < s) red[tid] += red[tid + s];
            __syncthreads();
        }
        if (tid == 0)
            g_gold = red[0] + (double)__ldg(&trans[(size_t)(L_LAB - 1) * L_LAB + __ldg(&ref[T_LEN - 1])]);
        return;
    }

    // ================= compute cluster (R10 structure; mbarrier sync) =================
    __shared__ __align__(16) float  sAlpha[2][L_LAB];  // exchanged alphas (parity)
    __shared__ __align__(16) __half sEh[L_LAB];        // e[i] = 2^(alpha[i]-m), fp16
    __shared__ __align__(8)  float  sOut[ROWS_PER_BLK];
    __shared__ float sRed[40];                         // warp maxima + broadcast slot
    __shared__ __align__(8) unsigned long long sBar[2];// parity mbarriers, count=16

    const int tid = threadIdx.x;
    const int w = tid >> 5, l = tid & 31;
    const unsigned rank = blockIdx.x;
    const int jA = (int)rank * ROWS_PER_BLK + 2 * w;   // warp's rows: jA, jA+1

    const unsigned barA0 = smem_u32(&sBar[0]);
    const unsigned barA1 = smem_u32(&sBar[1]);

    if (tid == 0) {
        asm volatile("mbarrier.init.shared.b64 [%0], %1;" :: "r"(barA0), "r"(CSIZE) : "memory");
        asm volatile("mbarrier.init.shared.b64 [%0], %1;" :: "r"(barA1), "r"(CSIZE) : "memory");
    }

    // ---- precompute expW = exp(W) for rows jA, jA+1, packed fp16.
    // Thread (w,l), chunk k2=0..3 covers labels i = k2*256 + 8l + m, m=0..7.
    __half2 hA[16], hB[16];
    {
        const float* ta = trans + (size_t)jA * L_LAB;
        const float* tb = ta + L_LAB;
        #pragma unroll
        for (int k2 = 0; k2 < 4; ++k2) {
            float4 u = *reinterpret_cast<const float4*>(ta + k2 * 256 + 8 * l);
            float4 v = *reinterpret_cast<const float4*>(ta + k2 * 256 + 8 * l + 4);
            hA[k2 * 4 + 0] = __floats2half2_rn(ex2f(u.x * LOG2E), ex2f(u.y * LOG2E));
            hA[k2 * 4 + 1] = __floats2half2_rn(ex2f(u.z * LOG2E), ex2f(u.w * LOG2E));
            hA[k2 * 4 + 2] = __floats2half2_rn(ex2f(v.x * LOG2E), ex2f(v.y * LOG2E));
            hA[k2 * 4 + 3] = __floats2half2_rn(ex2f(v.z * LOG2E), ex2f(v.w * LOG2E));
            u = *reinterpret_cast<const float4*>(tb + k2 * 256 + 8 * l);
            v = *reinterpret_cast<const float4*>(tb + k2 * 256 + 8 * l + 4);
            hB[k2 * 4 + 0] = __floats2half2_rn(ex2f(u.x * LOG2E), ex2f(u.y * LOG2E));
            hB[k2 * 4 + 1] = __floats2half2_rn(ex2f(u.z * LOG2E), ex2f(u.w * LOG2E));
            hB[k2 * 4 + 2] = __floats2half2_rn(ex2f(v.x * LOG2E), ex2f(v.y * LOG2E));
            hB[k2 * 4 + 3] = __floats2half2_rn(ex2f(v.z * LOG2E), ex2f(v.w * LOG2E));
        }
    }

    // ---- step 1 closed form: alpha2(1)[j] = (W[j,START] + pred[0,j]) * log2e
    float2 fcur, fnext;               // feats (lane 0 only)
    if (l == 0) {
        float wsA = __ldg(&trans[(size_t)jA * L_LAB + (L_LAB - 2)]);
        float wsB = __ldg(&trans[(size_t)(jA + 1) * L_LAB + (L_LAB - 2)]);
        float2 p0 = __ldg(reinterpret_cast<const float2*>(pred + jA));
        sOut[2 * w]     = (wsA + p0.x) * LOG2E;
        sOut[2 * w + 1] = (wsB + p0.y) * LOG2E;
        fcur = __ldg(reinterpret_cast<const float2*>(pred + (size_t)L_LAB + jA));
    }
    __syncthreads();                  // sOut complete + mbarrier init done (CTA-local)
    CLUSTER_SYNC();                   // all CTAs' mbarriers initialized before any arrive

    if (w < CSIZE) {                  // warp p pushes this block's chunk to peer p
        float2 f = *reinterpret_cast<float2*>(&sOut[2 * l]);
        unsigned long long v;
        asm("mov.b64 %0, {%1,%2};" : "=l"(v) : "f"(f.x), "f"(f.y));
        st_dsmem64(smem_u32(&sAlpha[1][rank * ROWS_PER_BLK + 2 * l]), (unsigned)w, v);
        __syncwarp();
        if (l == 0) mbar_arrive_peer(barA1, (unsigned)w);
    }

    double csum = 0.0;

    for (int t = 1; t < T_LEN; ++t) {
        const int buf = t & 1, nbuf = buf ^ 1;
        const unsigned parity = (unsigned)(((t - 1) >> 1) & 1);

        // ---- wait for all 16 chunks to land in OUR smem (point-to-point) ----
        mbar_wait_cluster(buf ? barA1 : barA0, parity);

        // ---- deterministic block max m (identical data+order on every CTA) ----
        float a = sAlpha[buf][tid];
        float mx = a;
        #pragma unroll
        for (int o = 16; o > 0; o >>= 1) mx = fmaxf(mx, __shfl_xor_sync(0xffffffffu, mx, o));
        if (l == 0) sRed[w] = mx;
        __syncthreads();
        if (tid < 32) {
            float mm = sRed[tid];
            #pragma unroll
            for (int o = 16; o > 0; o >>= 1) mm = fmaxf(mm, __shfl_xor_sync(0xffffffffu, mm, o));
            if (tid == 0) sRed[33] = mm;
        }
        __syncthreads();
        const float m = sRed[33];

        // e[i] = 2^(alpha[i]-m) <= 1  -> fp16 accumulation cannot overflow
        sEh[tid] = __float2half_rn(ex2f(a - m));
        if (rank == 0 && tid == 0) csum += (double)m;
        __syncthreads();

        if (l == 0 && t + 1 < T_LEN)
            fnext = __ldg(reinterpret_cast<const float2*>(pred + (size_t)(t + 1) * L_LAB + jA));

        // ---- rows jA, jA+1: s = sum_i expW[j,i]*e[i], packed half2 HFMA2 ----
        __half2 pA[4], pB[4];
        #pragma unroll
        for (int k2 = 0; k2 < 4; ++k2) {
            uint4 raw = *reinterpret_cast<const uint4*>(&sEh[k2 * 256 + 8 * l]);
            __half2 e0 = *reinterpret_cast<__half2*>(&raw.x);
            __half2 e1 = *reinterpret_cast<__half2*>(&raw.y);
            __half2 e2 = *reinterpret_cast<__half2*>(&raw.z);
            __half2 e3 = *reinterpret_cast<__half2*>(&raw.w);
            __half2 aa = __hmul2(e0, hA[k2 * 4 + 0]);
            aa = __hfma2(e1, hA[k2 * 4 + 1], aa);
            aa = __hfma2(e2, hA[k2 * 4 + 2], aa);
            aa = __hfma2(e3, hA[k2 * 4 + 3], aa);
            pA[k2] = aa;
            __half2 bb = __hmul2(e0, hB[k2 * 4 + 0]);
            bb = __hfma2(e1, hB[k2 * 4 + 1], bb);
            bb = __hfma2(e2, hB[k2 * 4 + 2], bb);
            bb = __hfma2(e3, hB[k2 * 4 + 3], bb);
            pB[k2] = bb;
        }
        __half2 hsA = __hadd2(__hadd2(pA[0], pA[1]), __hadd2(pA[2], pA[3]));
        __half2 hsB = __hadd2(__hadd2(pB[0], pB[1]), __hadd2(pB[2], pB[3]));
        float2 fa = __half22float2(hsA);
        float2 fb = __half22float2(hsB);
        float sA = fa.x + fa.y, sB = fb.x + fb.y;
        #pragma unroll
        for (int o = 16; o > 0; o >>= 1) {
            sA += __shfl_xor_sync(0xffffffffu, sA, o);
            sB += __shfl_xor_sync(0xffffffffu, sB, o);
        }

        if (l == 0) {
            sOut[2 * w]     = lg2f_(sA) + fcur.x * LOG2E;
            sOut[2 * w + 1] = lg2f_(sB) + fcur.y * LOG2E;
            fcur = fnext;
        }
        __syncthreads();              // sOut complete; also: sAlpha[buf]/sEh reads done

        // ---- push chunk to every peer; release-arrive rides with the data ----
        if (w < CSIZE) {
            float2 f = *reinterpret_cast<float2*>(&sOut[2 * l]);
            unsigned long long vv;
            asm("mov.b64 %0, {%1,%2};" : "=l"(vv) : "f"(f.x), "f"(f.y));
            st_dsmem64(smem_u32(&sAlpha[nbuf][rank * ROWS_PER_BLK + 2 * l]), (unsigned)w, vv);
            __syncwarp();
            if (l == 0) mbar_arrive_peer(nbuf ? barA1 : barA0, (unsigned)w);
        }
        // No trailing barrier needed: phase-t+2 arrivals/stores to buffer `buf`
        // cannot occur until every CTA consumed t+1, which requires our t+1
        // publish above (2-deep pipeline induction).
    }

    // alpha(T_LEN) landed in buffer 0; its wait-parity would be ((T_LEN-1)>>1)&1 = 1.
    if (rank == 0) {
        mbar_wait_cluster(barA0, 1u);
        g_alpha[tid] = sAlpha[0][tid];
        if (tid == 0) g_csum = csum;
    }
    CLUSTER_SYNC();   // no CTA exits while peers' DSMEM stores/arrives may be in flight
}

// Terminal: forward = LSE_j(alpha2(T)[j] + W2[STOP,j]) + csum, max-stabilized
// (the STOP row is uniformly -1e4; without the max everything underflows).
__global__ void crf_final(const float* __restrict__ trans, float* __restrict__ out)
{
    __shared__ float  sm[256];
    __shared__ double sd[256];
    int tid = threadIdx.x;

    float x[4];
    float m = -3.4e38f;
    #pragma unroll
    for (int q = 0; q < 4; ++q) {
        int jj = q * 256 + tid;
        float a  = g_alpha[jj];
        float wl = __ldg(&trans[(size_t)(L_LAB - 1) * L_LAB + jj]) * LOG2E;
        x[q] = a + wl;
        m = fmaxf(m, x[q]);
    }
    sm[tid] = m; __syncthreads();
    for (int s = 128; s > 0; s >>= 1) {
        if (tid < s) sm[tid] = fmaxf(sm[tid], sm[tid + s]);
        __syncthreads();
    }
    float M = sm[0];

    double loc = 0.0;
    #pragma unroll
    for (int q = 0; q < 4; ++q) loc += (double)ex2f(x[q] - M);
    sd[tid] = loc; __syncthreads();
    for (int s = 128; s > 0; s >>= 1) {
        if (tid < s) sd[tid] += sd[tid + s];
        __syncthreads();
    }
    if (tid == 0) {
        double fwd = (log2(sd[0]) + (double)M + g_csum) * LN2_D;
        out[0] = (float)(fwd - g_gold);
    }
}

extern "C" void kernel_launch(void* const* d_in, const int* in_sizes, int n_in,
                              void* d_out, int out_size)
{
    const float* pred = nullptr;
    const int*   ref  = nullptr;
    const float* trans = nullptr;
    for (int i = 0; i < n_in; ++i) {
        if (in_sizes[i] == T_LEN)                 ref   = (const int*)d_in[i];
        else if (in_sizes[i] == L_LAB * L_LAB)    trans = (const float*)d_in[i];
        else if (in_sizes[i] == T_LEN * L_LAB)    pred  = (const float*)d_in[i];
    }
    cudaFuncSetAttribute(crf_main, cudaFuncAttributeNonPortableClusterSizeAllowed, 1);

    dim3 grid(CSIZE, 2);
    crf_main<<<grid, TPB>>>(pred, ref, trans);
    crf_final<<<1, 256>>>(trans, (float*)d_out);
}